// round 14
// baseline (speedup 1.0000x reference)
#include <cuda_runtime.h>
#include <cstdint>

#define D 128
#define NMAX 50000
#define EMAX 800000

// ---------------- scratch (static device globals; no allocation) ----------------
__device__ float g_H [(size_t)NMAX * D];   // GEMM output per layer
__device__ float g_A [(size_t)NMAX * D];   // layer activations (ping)
__device__ float g_B [(size_t)NMAX * D];   // layer activations (pong)
__device__ float g_Wh[3 * D * D];          // pre-split W hi (tf32) per layer
__device__ float g_Wl[3 * D * D];          // pre-split W lo per layer
__device__ float g_dinv[NMAX];
__device__ int   g_cnt[NMAX];              // invariant: zero at entry of every call
__device__ int   g_rowstart[NMAX + 1];
__device__ int   g_cursor[NMAX];
__device__ int2  g_cw[EMAX];               // packed (src, weight-bits)
__device__ unsigned long long g_desc[64];  // lookback descriptors (zero at entry)

// ---------------- capture-safe static stream/events (host resources only) ------
static cudaStream_t s2;
static cudaEvent_t  evFork, evJoin;
namespace { struct _Init {
    _Init() {
        cudaStreamCreateWithFlags(&s2, cudaStreamNonBlocking);
        cudaEventCreateWithFlags(&evFork, cudaEventDisableTiming);
        cudaEventCreateWithFlags(&evJoin, cudaEventDisableTiming);
    }
} _init; }

// ---------------- tf32 / async helpers ----------------
__device__ __forceinline__ void tf32_split(float x, float& h, float& l) {
    uint32_t hb; asm("cvt.rna.tf32.f32 %0, %1;" : "=r"(hb) : "f"(x));
    h = __uint_as_float(hb);
    float r = x - h;
    uint32_t lb; asm("cvt.rna.tf32.f32 %0, %1;" : "=r"(lb) : "f"(r));
    l = __uint_as_float(lb);
}

__device__ __forceinline__ void mma_tf32(float* c, const uint32_t* a,
                                         uint32_t b0, uint32_t b1) {
    asm volatile(
        "mma.sync.aligned.m16n8k8.row.col.f32.tf32.tf32.f32 "
        "{%0,%1,%2,%3}, {%4,%5,%6,%7}, {%8,%9}, {%0,%1,%2,%3};"
        : "+f"(c[0]), "+f"(c[1]), "+f"(c[2]), "+f"(c[3])
        : "r"(a[0]), "r"(a[1]), "r"(a[2]), "r"(a[3]), "r"(b0), "r"(b1));
}

__device__ __forceinline__ void cp_async16(uint32_t saddr, const void* gptr) {
    asm volatile("cp.async.cg.shared.global [%0], [%1], 16;"
                 :: "r"(saddr), "l"(gptr));
}

// ---------------- W pre-split: all 3 layers in one launch ----------------
__global__ void k_wsplit(const float* __restrict__ W1,
                         const float* __restrict__ W2,
                         const float* __restrict__ W3) {
    int layer = blockIdx.y;
    const float* W = (layer == 0) ? W1 : (layer == 1) ? W2 : W3;
    int i = blockIdx.x * 256 + threadIdx.x;      // 0..16383 (grid.x = 64)
    float h, l;
    tf32_split(W[i], h, l);
    g_Wh[layer * D * D + i] = h;
    g_Wl[layer * D * D + i] = l;
}

// ---------------- CSR construction ----------------
__global__ void k_count(const int* __restrict__ dst, int E) {
    int base = (blockIdx.x * blockDim.x + threadIdx.x) * 4;
    if (base >= E) return;
    if (base + 3 < E) {
        int4 d = *(const int4*)(dst + base);
        atomicAdd(&g_cnt[d.x], 1);
        atomicAdd(&g_cnt[d.y], 1);
        atomicAdd(&g_cnt[d.z], 1);
        atomicAdd(&g_cnt[d.w], 1);
    } else {
        for (int j = base; j < E; j++) atomicAdd(&g_cnt[dst[j]], 1);
    }
}

// single-pass exclusive scan via decoupled lookback; writes rowstart/cursor/dinv.
// Also re-zeroes g_cnt (self-cleaning invariant). 49 blocks <= 148 SMs.
__global__ void k_scan_lb(int n) {
    __shared__ int wsum[32];
    __shared__ int s_prefix;
    int tid = threadIdx.x, lane = tid & 31, wid = tid >> 5;
    int b = blockIdx.x;
    int i = b * 1024 + tid;
    int v = (i < n) ? g_cnt[i] : 0;
    if (i < n) g_cnt[i] = 0;               // self-clean for next replay
    int x = v;
    #pragma unroll
    for (int o = 1; o < 32; o <<= 1) {
        int t = __shfl_up_sync(0xffffffffu, x, o);
        if (lane >= o) x += t;
    }
    if (lane == 31) wsum[wid] = x;
    __syncthreads();
    if (wid == 0) {
        int w = wsum[lane];
        #pragma unroll
        for (int o = 1; o < 32; o <<= 1) {
            int t = __shfl_up_sync(0xffffffffu, w, o);
            if (lane >= o) w += t;
        }
        wsum[lane] = w;
    }
    __syncthreads();
    int blockAgg = wsum[31];

    if (tid == 0) {
        if (b == 0) {
            s_prefix = 0;
            atomicExch(&g_desc[0], (2ULL << 32) | (unsigned)blockAgg);
        } else {
            atomicExch(&g_desc[b], (1ULL << 32) | (unsigned)blockAgg);
        }
    }
    if (b > 0 && wid == 0) {
        int prefix = 0;
        int look = b - 1;
        while (true) {
            int idx = look - lane;
            unsigned f; int val;
            if (idx >= 0) {
                unsigned long long d = atomicAdd(&g_desc[idx], 0ULL);
                f = (unsigned)(d >> 32);
                val = (int)(unsigned)d;
            } else { f = 1u; val = 0; }
            if (__ballot_sync(0xffffffffu, f == 0u)) continue;   // retry window
            unsigned bp = __ballot_sync(0xffffffffu, idx >= 0 && f == 2u);
            int stop = bp ? (__ffs(bp) - 1) : 32;
            int xs = (lane <= stop) ? val : 0;
            #pragma unroll
            for (int o = 16; o > 0; o >>= 1)
                xs += __shfl_xor_sync(0xffffffffu, xs, o);
            prefix += xs;
            if (stop < 32) break;
            look -= 32;
        }
        if (lane == 0) {
            s_prefix = prefix;
            atomicExch(&g_desc[b], (2ULL << 32) | (unsigned)(prefix + blockAgg));
        }
    }
    __syncthreads();

    int excl = s_prefix + (wid ? wsum[wid - 1] : 0) + x - v;
    if (i < n) {
        g_rowstart[i] = excl;
        g_cursor[i]   = excl;
        g_dinv[i]     = rsqrtf((float)(v + 1));   // deg incl. self-loop
        if (i == n - 1) g_rowstart[n] = excl + v;
    }
}

__global__ void k_fill(const int* __restrict__ ei, int E) {
    // re-zero lookback descriptors for next replay (scan complete)
    if (blockIdx.x == 0 && threadIdx.x < 64) g_desc[threadIdx.x] = 0ULL;
    int base = (blockIdx.x * blockDim.x + threadIdx.x) * 4;
    if (base >= E) return;
    if (base + 3 < E) {
        int4 s = *(const int4*)(ei + base);
        int4 d = *(const int4*)(ei + E + base);
        int ss[4] = {s.x, s.y, s.z, s.w};
        int ds[4] = {d.x, d.y, d.z, d.w};
        float ws[4];
        #pragma unroll
        for (int j = 0; j < 4; j++) ws[j] = g_dinv[ss[j]] * g_dinv[ds[j]];
        #pragma unroll
        for (int j = 0; j < 4; j++) {
            int p = atomicAdd(&g_cursor[ds[j]], 1);
            g_cw[p] = make_int2(ss[j], __float_as_int(ws[j]));
        }
    } else {
        for (int j = base; j < E; j++) {
            int sj = ei[j], dj = ei[E + j];
            float w = g_dinv[sj] * g_dinv[dj];
            int p = atomicAdd(&g_cursor[dj], 1);
            g_cw[p] = make_int2(sj, __float_as_int(w));
        }
    }
}

// ---------------- GEMM: H[M x 128] = X @ W via 3xTF32 mma.m16n8k8 ----------------
// Block tile M=128, N=128; 512 threads = 16 warps: 8(M) x 2(N); warp tile 16x64.
// Small warp tile -> acc=32 regs -> ~100 regs/thread -> 16 warps/SM (4/SMSP),
// double the issue slots of the 8-warp config (which was issue-bound at 23.6%).
// W pre-split in gmem; copied ONCE per block (full K) via cp.async (pure copy).
#define SXS 68    // X smem row stride: A-frag bank = (4g+t)%32, bijective
#define SWS 136   // W smem row stride: B-frag bank = (8t+g)%32, bijective
#define GEMM_SMEM ((2 * 128 * SXS + 2 * 128 * SWS) * (int)sizeof(float))
#define GT 512

__global__ __launch_bounds__(GT, 1)
void k_gemm_mma(const float* __restrict__ X,
                const float* __restrict__ Wh, const float* __restrict__ Wl,
                float* __restrict__ H, int M) {
    extern __shared__ float sm[];
    float* sXh = sm;
    float* sXl = sXh + 128 * SXS;
    float* sWh = sXl + 128 * SXS;           // full K=128 rows
    float* sWl = sWh + 128 * SWS;

    const int tid  = threadIdx.x;
    const int lane = tid & 31;
    const int g    = lane >> 2;
    const int t    = lane & 3;
    const int warp = tid >> 5;              // 0..15
    const int wm   = (warp >> 1) * 16;      // warp M offset (8 warps in M)
    const int wn   = (warp & 1) * 64;       // warp N offset (2 in N)
    const int row0 = blockIdx.x * 128;

    // ---- async copy of both W splits (full K), overlapped with X chunk 0 load
    {
        uint32_t swh = (uint32_t)__cvta_generic_to_shared(sWh);
        uint32_t swl = (uint32_t)__cvta_generic_to_shared(sWl);
        #pragma unroll
        for (int it = 0; it < 8; it++) {
            int e4 = tid + it * GT;         // 0..4095
            int r  = e4 >> 5;               // k row 0..127
            int c4 = (e4 & 31) * 4;         // n col
            cp_async16(swh + (uint32_t)(r * SWS + c4) * 4, Wh + r * D + c4);
            cp_async16(swl + (uint32_t)(r * SWS + c4) * 4, Wl + r * D + c4);
        }
        asm volatile("cp.async.commit_group;");
    }

    float acc[8][4];
    #pragma unroll
    for (int b = 0; b < 8; b++)
        #pragma unroll
        for (int c = 0; c < 4; c++) acc[b][c] = 0.f;

    #pragma unroll
    for (int kc = 0; kc < 2; kc++) {
        // load + split X chunk [128 rows][64 k]; 2048 float4 over 512 threads
        #pragma unroll
        for (int it = 0; it < 4; it++) {
            int e4 = tid + it * GT;
            int r  = e4 >> 4;
            int c4 = (e4 & 15) * 4;
            float4 v = make_float4(0.f, 0.f, 0.f, 0.f);
            if (row0 + r < M)
                v = *(const float4*)&X[(size_t)(row0 + r) * D + kc * 64 + c4];
            float4 h, l;
            tf32_split(v.x, h.x, l.x);
            tf32_split(v.y, h.y, l.y);
            tf32_split(v.z, h.z, l.z);
            tf32_split(v.w, h.w, l.w);
            *(float4*)&sXh[r * SXS + c4] = h;
            *(float4*)&sXl[r * SXS + c4] = l;
        }
        if (kc == 0) asm volatile("cp.async.wait_group 0;");
        __syncthreads();

        #pragma unroll
        for (int ks = 0; ks < 8; ks++) {
            int k0 = ks * 8;            // local X k
            int kg = kc * 64 + k0;      // global W k row
            uint32_t ah[4], al[4];
            ah[0] = __float_as_uint(sXh[(wm + g)     * SXS + k0 + t]);
            ah[1] = __float_as_uint(sXh[(wm + g + 8) * SXS + k0 + t]);
            ah[2] = __float_as_uint(sXh[(wm + g)     * SXS + k0 + t + 4]);
            ah[3] = __float_as_uint(sXh[(wm + g + 8) * SXS + k0 + t + 4]);
            al[0] = __float_as_uint(sXl[(wm + g)     * SXS + k0 + t]);
            al[1] = __float_as_uint(sXl[(wm + g + 8) * SXS + k0 + t]);
            al[2] = __float_as_uint(sXl[(wm + g)     * SXS + k0 + t + 4]);
            al[3] = __float_as_uint(sXl[(wm + g + 8) * SXS + k0 + t + 4]);
            // preload all B fragments for this warp's N-half
            uint32_t bh[8][2], bl[8][2];
            #pragma unroll
            for (int j = 0; j < 8; j++) {
                int nb = wn + j * 8;
                bh[j][0] = __float_as_uint(sWh[(kg + t)     * SWS + nb + g]);
                bh[j][1] = __float_as_uint(sWh[(kg + t + 4) * SWS + nb + g]);
                bl[j][0] = __float_as_uint(sWl[(kg + t)     * SWS + nb + g]);
                bl[j][1] = __float_as_uint(sWl[(kg + t + 4) * SWS + nb + g]);
            }
            // three passes of 8 independent mmas (acc reuse distance = 8)
            #pragma unroll
            for (int j = 0; j < 8; j++)
                mma_tf32(acc[j], ah, bh[j][0], bh[j][1]);
            #pragma unroll
            for (int j = 0; j < 8; j++)
                mma_tf32(acc[j], ah, bl[j][0], bl[j][1]);
            #pragma unroll
            for (int j = 0; j < 8; j++)
                mma_tf32(acc[j], al, bh[j][0], bh[j][1]);
        }
        __syncthreads();
    }

    int r0 = row0 + wm + g;
    #pragma unroll
    for (int j = 0; j < 8; j++) {
        int col = wn + j * 8 + 2 * t;
        if (r0 < M)
            *(float2*)&H[(size_t)r0 * D + col] = make_float2(acc[j][0], acc[j][1]);
        if (r0 + 8 < M)
            *(float2*)&H[(size_t)(r0 + 8) * D + col] = make_float2(acc[j][2], acc[j][3]);
    }
}

// ---------------- aggregation: Y[n] = relu?( dinv^2*H[n] + sum w_i*H[col_i] + b )
__global__ void k_agg(const float* __restrict__ bias, float* __restrict__ Y,
                      int n, int do_relu) {
    int gt   = blockIdx.x * blockDim.x + threadIdx.x;
    int node = gt >> 5;
    int lane = gt & 31;
    if (node >= n) return;

    const float4* H4 = (const float4*)g_H;
    float di = g_dinv[node];
    float4 acc = H4[(size_t)node * 32 + lane];
    float sw = di * di;
    acc.x *= sw; acc.y *= sw; acc.z *= sw; acc.w *= sw;

    int i   = g_rowstart[node];
    int end = g_rowstart[node + 1];
    for (; i + 3 < end; i += 4) {
        int2  e0 = g_cw[i],     e1 = g_cw[i + 1];
        int2  e2 = g_cw[i + 2], e3 = g_cw[i + 3];
        float w0 = __int_as_float(e0.y), w1 = __int_as_float(e1.y);
        float w2 = __int_as_float(e2.y), w3 = __int_as_float(e3.y);
        float4 h0 = H4[(size_t)e0.x * 32 + lane];
        float4 h1 = H4[(size_t)e1.x * 32 + lane];
        float4 h2 = H4[(size_t)e2.x * 32 + lane];
        float4 h3 = H4[(size_t)e3.x * 32 + lane];
        acc.x += w0 * h0.x + w1 * h1.x + w2 * h2.x + w3 * h3.x;
        acc.y += w0 * h0.y + w1 * h1.y + w2 * h2.y + w3 * h3.y;
        acc.z += w0 * h0.z + w1 * h1.z + w2 * h2.z + w3 * h3.z;
        acc.w += w0 * h0.w + w1 * h1.w + w2 * h2.w + w3 * h3.w;
    }
    for (; i < end; i++) {
        int2  e = g_cw[i];
        float w = __int_as_float(e.y);
        float4 h = H4[(size_t)e.x * 32 + lane];
        acc.x += w * h.x; acc.y += w * h.y; acc.z += w * h.z; acc.w += w * h.w;
    }

    float4 b4 = ((const float4*)bias)[lane];
    acc.x += b4.x; acc.y += b4.y; acc.z += b4.z; acc.w += b4.w;
    if (do_relu) {
        acc.x = fmaxf(acc.x, 0.f); acc.y = fmaxf(acc.y, 0.f);
        acc.z = fmaxf(acc.z, 0.f); acc.w = fmaxf(acc.w, 0.f);
    }
    ((float4*)Y)[(size_t)node * 32 + lane] = acc;
}

// ---------------- decoder: out[e] = dot(X[u], X[v]) ----------------
__global__ void k_decode(const float* __restrict__ X, const int* __restrict__ eli,
                         float* __restrict__ out, int EL) {
    int gt   = blockIdx.x * blockDim.x + threadIdx.x;
    int e    = gt >> 5;
    int lane = gt & 31;
    if (e >= EL) return;
    int u = eli[e];
    int v = eli[EL + e];
    const float4* X4 = (const float4*)X;
    float4 a = X4[(size_t)u * 32 + lane];
    float4 b = X4[(size_t)v * 32 + lane];
    float s = a.x * b.x + a.y * b.y + a.z * b.z + a.w * b.w;
    #pragma unroll
    for (int o = 16; o > 0; o >>= 1) s += __shfl_xor_sync(0xffffffffu, s, o);
    if (lane == 0) out[e] = s;
}

// ---------------- launch ----------------
extern "C" void kernel_launch(void* const* d_in, const int* in_sizes, int n_in,
                              void* d_out, int out_size) {
    const float* x   = (const float*)d_in[0];
    const float* W1  = (const float*)d_in[1];
    const float* b1  = (const float*)d_in[2];
    const float* W2  = (const float*)d_in[3];
    const float* b2  = (const float*)d_in[4];
    const float* W3  = (const float*)d_in[5];
    const float* b3  = (const float*)d_in[6];
    const int*   ei  = (const int*)d_in[7];
    const int*   eli = (const int*)d_in[8];
    float*       out = (float*)d_out;

    int N  = in_sizes[0] / D;
    int E  = in_sizes[7] / 2;
    int EL = in_sizes[8] / 2;

    float *pH, *pA, *pB, *pWh, *pWl;
    cudaGetSymbolAddress((void**)&pH,  g_H);
    cudaGetSymbolAddress((void**)&pA,  g_A);
    cudaGetSymbolAddress((void**)&pB,  g_B);
    cudaGetSymbolAddress((void**)&pWh, g_Wh);
    cudaGetSymbolAddress((void**)&pWl, g_Wl);

    cudaFuncSetAttribute(k_gemm_mma, cudaFuncAttributeMaxDynamicSharedMemorySize,
                         GEMM_SMEM);

    int nb          = (N + 1023) / 1024;
    int gemm_blocks = (N + 127) / 128;
    int agg_blocks  = (int)(((size_t)N * 32 + 255) / 256);

    // ---- fork: CSR build on s2, concurrent with W-split + GEMM-1 on stream 0 ----
    cudaEventRecord(evFork, 0);
    cudaStreamWaitEvent(s2, evFork, 0);
    k_count  <<<(E / 4 + 255) / 256, 256, 0, s2>>>(ei + E, E);
    k_scan_lb<<<nb, 1024, 0, s2>>>(N);
    k_fill   <<<(E / 4 + 255) / 256, 256, 0, s2>>>(ei, E);
    cudaEventRecord(evJoin, s2);

    // ---- W pre-split (all layers) then layer-1 GEMM, overlapping CSR ----
    k_wsplit<<<dim3(64, 3), 256>>>(W1, W2, W3);
    k_gemm_mma<<<gemm_blocks, GT, GEMM_SMEM>>>(x, pWh, pWl, pH, N);

    // ---- join: agg needs both GEMM-1 output and the CSR ----
    cudaStreamWaitEvent(0, evJoin, 0);
    k_agg<<<agg_blocks, 256>>>(b1, pA, N, 1);

    // ---- layer 2 ----
    k_gemm_mma<<<gemm_blocks, GT, GEMM_SMEM>>>(pA, pWh + D * D, pWl + D * D, pH, N);
    k_agg<<<agg_blocks, 256>>>(b2, pB, N, 1);

    // ---- layer 3 (no relu) ----
    k_gemm_mma<<<gemm_blocks, GT, GEMM_SMEM>>>(pB, pWh + 2 * D * D, pWl + 2 * D * D, pH, N);
    k_agg<<<agg_blocks, 256>>>(b3, pA, N, 0);

    // ---- decoder ----
    k_decode<<<(int)(((size_t)EL * 32 + 255) / 256), 256>>>(pA, eli, out, EL);
}

// round 15
// speedup vs baseline: 1.3144x; 1.3144x over previous
#include <cuda_runtime.h>
#include <cuda_bf16.h>
#include <cstdint>

#define D 128
#define NMAX 50000
#define EMAX 800000

// ---------------- scratch (static device globals; no allocation) ----------------
__device__ float    g_H [(size_t)NMAX * D];   // GEMM output per layer
__device__ float    g_A [(size_t)NMAX * D];   // layer activations (ping)
__device__ float    g_B [(size_t)NMAX * D];   // layer activations (pong)
__device__ uint32_t g_Wh[3 * 64 * 128];       // W hi, packed bf16 k-pairs [p][n]
__device__ uint32_t g_Wl[3 * 64 * 128];       // W lo, packed bf16 k-pairs
__device__ float    g_dinv[NMAX];
__device__ int      g_cnt[NMAX];              // invariant: zero at entry
__device__ int      g_rowstart[NMAX + 1];
__device__ int      g_cursor[NMAX];
__device__ int2     g_cw[EMAX];               // packed (src, weight-bits)
__device__ unsigned long long g_desc[64];     // lookback descriptors (zero at entry)

// ---------------- capture-safe static stream/events (host resources only) ------
static cudaStream_t s2;
static cudaEvent_t  evFork, evJoin;
namespace { struct _Init {
    _Init() {
        cudaStreamCreateWithFlags(&s2, cudaStreamNonBlocking);
        cudaEventCreateWithFlags(&evFork, cudaEventDisableTiming);
        cudaEventCreateWithFlags(&evJoin, cudaEventDisableTiming);
    }
} _init; }

// ---------------- bf16 / mma / async helpers ----------------
// split a float2 (consecutive k) into packed bf16x2 hi and lo parts
__device__ __forceinline__ void bf16_split2(float2 v, uint32_t& hp, uint32_t& lp) {
    __nv_bfloat162 h2 = __float22bfloat162_rn(v);          // low=v.x, high=v.y
    float2 r = make_float2(v.x - __low2float(h2), v.y - __high2float(h2));
    __nv_bfloat162 l2 = __float22bfloat162_rn(r);
    hp = *reinterpret_cast<uint32_t*>(&h2);
    lp = *reinterpret_cast<uint32_t*>(&l2);
}

__device__ __forceinline__ void mma_bf16(float* c, const uint32_t* a,
                                         uint32_t b0, uint32_t b1) {
    asm volatile(
        "mma.sync.aligned.m16n8k16.row.col.f32.bf16.bf16.f32 "
        "{%0,%1,%2,%3}, {%4,%5,%6,%7}, {%8,%9}, {%0,%1,%2,%3};"
        : "+f"(c[0]), "+f"(c[1]), "+f"(c[2]), "+f"(c[3])
        : "r"(a[0]), "r"(a[1]), "r"(a[2]), "r"(a[3]), "r"(b0), "r"(b1));
}

__device__ __forceinline__ void cp_async16(uint32_t saddr, const void* gptr) {
    asm volatile("cp.async.cg.shared.global [%0], [%1], 16;"
                 :: "r"(saddr), "l"(gptr));
}

// ---------------- W pre-split: pack bf16 k-pairs, all 3 layers ----------------
// output [layer][p][n]: pair p covers k = 2p, 2p+1 (column n), low half = even k
__global__ void k_wsplit(const float* __restrict__ W1,
                         const float* __restrict__ W2,
                         const float* __restrict__ W3) {
    int layer = blockIdx.y;
    const float* W = (layer == 0) ? W1 : (layer == 1) ? W2 : W3;
    int i = blockIdx.x * 256 + threadIdx.x;      // 0..8191 (grid.x = 32)
    int p = i >> 7, n = i & 127;
    float x0 = W[(2 * p) * D + n];
    float x1 = W[(2 * p + 1) * D + n];
    uint32_t hp, lp;
    bf16_split2(make_float2(x0, x1), hp, lp);
    g_Wh[layer * 8192 + i] = hp;
    g_Wl[layer * 8192 + i] = lp;
}

// ---------------- CSR construction ----------------
__global__ void k_count(const int* __restrict__ dst, int E) {
    int base = (blockIdx.x * blockDim.x + threadIdx.x) * 4;
    if (base >= E) return;
    if (base + 3 < E) {
        int4 d = *(const int4*)(dst + base);
        atomicAdd(&g_cnt[d.x], 1);
        atomicAdd(&g_cnt[d.y], 1);
        atomicAdd(&g_cnt[d.z], 1);
        atomicAdd(&g_cnt[d.w], 1);
    } else {
        for (int j = base; j < E; j++) atomicAdd(&g_cnt[dst[j]], 1);
    }
}

// single-pass exclusive scan via decoupled lookback; self-cleans g_cnt.
__global__ void k_scan_lb(int n) {
    __shared__ int wsum[32];
    __shared__ int s_prefix;
    int tid = threadIdx.x, lane = tid & 31, wid = tid >> 5;
    int b = blockIdx.x;
    int i = b * 1024 + tid;
    int v = (i < n) ? g_cnt[i] : 0;
    if (i < n) g_cnt[i] = 0;               // self-clean for next replay
    int x = v;
    #pragma unroll
    for (int o = 1; o < 32; o <<= 1) {
        int t = __shfl_up_sync(0xffffffffu, x, o);
        if (lane >= o) x += t;
    }
    if (lane == 31) wsum[wid] = x;
    __syncthreads();
    if (wid == 0) {
        int w = wsum[lane];
        #pragma unroll
        for (int o = 1; o < 32; o <<= 1) {
            int t = __shfl_up_sync(0xffffffffu, w, o);
            if (lane >= o) w += t;
        }
        wsum[lane] = w;
    }
    __syncthreads();
    int blockAgg = wsum[31];

    if (tid == 0) {
        if (b == 0) {
            s_prefix = 0;
            atomicExch(&g_desc[0], (2ULL << 32) | (unsigned)blockAgg);
        } else {
            atomicExch(&g_desc[b], (1ULL << 32) | (unsigned)blockAgg);
        }
    }
    if (b > 0 && wid == 0) {
        int prefix = 0;
        int look = b - 1;
        while (true) {
            int idx = look - lane;
            unsigned f; int val;
            if (idx >= 0) {
                unsigned long long d = atomicAdd(&g_desc[idx], 0ULL);
                f = (unsigned)(d >> 32);
                val = (int)(unsigned)d;
            } else { f = 1u; val = 0; }
            if (__ballot_sync(0xffffffffu, f == 0u)) continue;   // retry window
            unsigned bp = __ballot_sync(0xffffffffu, idx >= 0 && f == 2u);
            int stop = bp ? (__ffs(bp) - 1) : 32;
            int xs = (lane <= stop) ? val : 0;
            #pragma unroll
            for (int o = 16; o > 0; o >>= 1)
                xs += __shfl_xor_sync(0xffffffffu, xs, o);
            prefix += xs;
            if (stop < 32) break;
            look -= 32;
        }
        if (lane == 0) {
            s_prefix = prefix;
            atomicExch(&g_desc[b], (2ULL << 32) | (unsigned)(prefix + blockAgg));
        }
    }
    __syncthreads();

    int excl = s_prefix + (wid ? wsum[wid - 1] : 0) + x - v;
    if (i < n) {
        g_rowstart[i] = excl;
        g_cursor[i]   = excl;
        g_dinv[i]     = rsqrtf((float)(v + 1));   // deg incl. self-loop
        if (i == n - 1) g_rowstart[n] = excl + v;
    }
}

__global__ void k_fill(const int* __restrict__ ei, int E) {
    // re-zero lookback descriptors for next replay (scan complete)
    if (blockIdx.x == 0 && threadIdx.x < 64) g_desc[threadIdx.x] = 0ULL;
    int base = (blockIdx.x * blockDim.x + threadIdx.x) * 4;
    if (base >= E) return;
    if (base + 3 < E) {
        int4 s = *(const int4*)(ei + base);
        int4 d = *(const int4*)(ei + E + base);
        int ss[4] = {s.x, s.y, s.z, s.w};
        int ds[4] = {d.x, d.y, d.z, d.w};
        float ws[4];
        #pragma unroll
        for (int j = 0; j < 4; j++) ws[j] = g_dinv[ss[j]] * g_dinv[ds[j]];
        #pragma unroll
        for (int j = 0; j < 4; j++) {
            int p = atomicAdd(&g_cursor[ds[j]], 1);
            g_cw[p] = make_int2(ss[j], __float_as_int(ws[j]));
        }
    } else {
        for (int j = base; j < E; j++) {
            int sj = ei[j], dj = ei[E + j];
            float w = g_dinv[sj] * g_dinv[dj];
            int p = atomicAdd(&g_cursor[dj], 1);
            g_cw[p] = make_int2(sj, __float_as_int(w));
        }
    }
}

// ---------------- GEMM: H[M x 128] = X @ W via 3x bf16 mma.m16n8k16 -------------
// R12-measured structure (8 warps: 4(M) x 2(N), warp tile 32x64, occ 1), dtype
// swapped tf32->bf16: K=16 per mma halves both fragment-LDS and mma counts.
// Fragment layouts mirror tf32-k8 with k-PAIRS; indexing/strides carry over.
#define SXB 36    // X smem row stride (uint32 pairs): A bank = (4g+t)%32 bijective
#define SWB 136   // W smem row stride (uint32):       B bank = (8t+g)%32 bijective
#define GEMM_SMEM ((2 * 128 * SXB + 2 * 64 * SWB) * (int)sizeof(uint32_t))

__global__ __launch_bounds__(256, 1)
void k_gemm_mma(const float* __restrict__ X,
                const uint32_t* __restrict__ Wh, const uint32_t* __restrict__ Wl,
                float* __restrict__ H, int M) {
    extern __shared__ uint32_t smu[];
    uint32_t* sXh = smu;
    uint32_t* sXl = sXh + 128 * SXB;
    uint32_t* sWh = sXl + 128 * SXB;        // full K: 64 pair-rows
    uint32_t* sWl = sWh + 64 * SWB;

    const int tid  = threadIdx.x;
    const int lane = tid & 31;
    const int g    = lane >> 2;
    const int t    = lane & 3;
    const int warp = tid >> 5;
    const int wm   = (warp >> 1) * 32;   // warp M offset
    const int wn   = (warp & 1) * 64;    // warp N offset
    const int row0 = blockIdx.x * 128;

    // ---- async copy of both W splits (full K, pre-packed; pure copy)
    {
        uint32_t swh = (uint32_t)__cvta_generic_to_shared(sWh);
        uint32_t swl = (uint32_t)__cvta_generic_to_shared(sWl);
        #pragma unroll
        for (int it = 0; it < 8; it++) {
            int e4 = tid + it * 256;        // 0..2047 (16B chunks)
            int r  = e4 >> 5;               // pair row 0..63
            int c4 = (e4 & 31) * 4;         // n col (x4 uint32)
            cp_async16(swh + (uint32_t)(r * SWB + c4) * 4, Wh + r * 128 + c4);
            cp_async16(swl + (uint32_t)(r * SWB + c4) * 4, Wl + r * 128 + c4);
        }
        asm volatile("cp.async.commit_group;");
    }

    float acc[2][8][4];
    #pragma unroll
    for (int a = 0; a < 2; a++)
        #pragma unroll
        for (int b = 0; b < 8; b++)
            #pragma unroll
            for (int c = 0; c < 4; c++) acc[a][b][c] = 0.f;

    #pragma unroll
    for (int kc = 0; kc < 2; kc++) {
        // load + split X chunk [128 rows][64 k = 32 pairs]
        #pragma unroll
        for (int it = 0; it < 8; it++) {
            int e4 = tid + it * 256;        // 0..2047
            int r  = e4 >> 4;               // row 0..127
            int c4 = e4 & 15;               // float4 index in row (16 per row)
            float4 v = make_float4(0.f, 0.f, 0.f, 0.f);
            if (row0 + r < M)
                v = *(const float4*)&X[(size_t)(row0 + r) * D + kc * 64 + c4 * 4];
            uint32_t hp0, lp0, hp1, lp1;
            bf16_split2(make_float2(v.x, v.y), hp0, lp0);
            bf16_split2(make_float2(v.z, v.w), hp1, lp1);
            *(uint2*)&sXh[r * SXB + c4 * 2] = make_uint2(hp0, hp1);
            *(uint2*)&sXl[r * SXB + c4 * 2] = make_uint2(lp0, lp1);
        }
        if (kc == 0) asm volatile("cp.async.wait_group 0;");
        __syncthreads();

        #pragma unroll
        for (int ks = 0; ks < 4; ks++) {       // 4 x K16 per 64-k chunk
            int kp  = ks * 8;                  // pair offset in chunk
            int kgp = kc * 32 + kp;            // global W pair row
            uint32_t ah[2][4], al[2][4];
            #pragma unroll
            for (int mi = 0; mi < 2; mi++) {
                int mb = wm + mi * 16;
                ah[mi][0] = sXh[(mb + g)     * SXB + kp + t];
                ah[mi][1] = sXh[(mb + g + 8) * SXB + kp + t];
                ah[mi][2] = sXh[(mb + g)     * SXB + kp + t + 4];
                ah[mi][3] = sXh[(mb + g + 8) * SXB + kp + t + 4];
                al[mi][0] = sXl[(mb + g)     * SXB + kp + t];
                al[mi][1] = sXl[(mb + g + 8) * SXB + kp + t];
                al[mi][2] = sXl[(mb + g)     * SXB + kp + t + 4];
                al[mi][3] = sXl[(mb + g + 8) * SXB + kp + t + 4];
            }
            #pragma unroll
            for (int j = 0; j < 8; j++) {
                int nb = wn + j * 8;
                uint32_t bh0 = sWh[(kgp + t)     * SWB + nb + g];
                uint32_t bh1 = sWh[(kgp + t + 4) * SWB + nb + g];
                uint32_t bl0 = sWl[(kgp + t)     * SWB + nb + g];
                uint32_t bl1 = sWl[(kgp + t + 4) * SWB + nb + g];
                #pragma unroll
                for (int mi = 0; mi < 2; mi++) {
                    mma_bf16(acc[mi][j], ah[mi], bh0, bh1);
                    mma_bf16(acc[mi][j], ah[mi], bl0, bl1);
                    mma_bf16(acc[mi][j], al[mi], bh0, bh1);
                }
            }
        }
        __syncthreads();
    }

    #pragma unroll
    for (int mi = 0; mi < 2; mi++) {
        int r0 = row0 + wm + mi * 16 + g;
        #pragma unroll
        for (int j = 0; j < 8; j++) {
            int col = wn + j * 8 + 2 * t;
            if (r0 < M)
                *(float2*)&H[(size_t)r0 * D + col] =
                    make_float2(acc[mi][j][0], acc[mi][j][1]);
            if (r0 + 8 < M)
                *(float2*)&H[(size_t)(r0 + 8) * D + col] =
                    make_float2(acc[mi][j][2], acc[mi][j][3]);
        }
    }
}

// ---------------- aggregation: Y[n] = relu?( dinv^2*H[n] + sum w_i*H[col_i] + b )
__global__ void k_agg(const float* __restrict__ bias, float* __restrict__ Y,
                      int n, int do_relu) {
    int gt   = blockIdx.x * blockDim.x + threadIdx.x;
    int node = gt >> 5;
    int lane = gt & 31;
    if (node >= n) return;

    const float4* H4 = (const float4*)g_H;
    float di = g_dinv[node];
    float4 acc = H4[(size_t)node * 32 + lane];
    float sw = di * di;
    acc.x *= sw; acc.y *= sw; acc.z *= sw; acc.w *= sw;

    int i   = g_rowstart[node];
    int end = g_rowstart[node + 1];
    for (; i + 3 < end; i += 4) {
        int2  e0 = g_cw[i],     e1 = g_cw[i + 1];
        int2  e2 = g_cw[i + 2], e3 = g_cw[i + 3];
        float w0 = __int_as_float(e0.y), w1 = __int_as_float(e1.y);
        float w2 = __int_as_float(e2.y), w3 = __int_as_float(e3.y);
        float4 h0 = H4[(size_t)e0.x * 32 + lane];
        float4 h1 = H4[(size_t)e1.x * 32 + lane];
        float4 h2 = H4[(size_t)e2.x * 32 + lane];
        float4 h3 = H4[(size_t)e3.x * 32 + lane];
        acc.x += w0 * h0.x + w1 * h1.x + w2 * h2.x + w3 * h3.x;
        acc.y += w0 * h0.y + w1 * h1.y + w2 * h2.y + w3 * h3.y;
        acc.z += w0 * h0.z + w1 * h1.z + w2 * h2.z + w3 * h3.z;
        acc.w += w0 * h0.w + w1 * h1.w + w2 * h2.w + w3 * h3.w;
    }
    for (; i < end; i++) {
        int2  e = g_cw[i];
        float w = __int_as_float(e.y);
        float4 h = H4[(size_t)e.x * 32 + lane];
        acc.x += w * h.x; acc.y += w * h.y; acc.z += w * h.z; acc.w += w * h.w;
    }

    float4 b4 = ((const float4*)bias)[lane];
    acc.x += b4.x; acc.y += b4.y; acc.z += b4.z; acc.w += b4.w;
    if (do_relu) {
        acc.x = fmaxf(acc.x, 0.f); acc.y = fmaxf(acc.y, 0.f);
        acc.z = fmaxf(acc.z, 0.f); acc.w = fmaxf(acc.w, 0.f);
    }
    ((float4*)Y)[(size_t)node * 32 + lane] = acc;
}

// ---------------- decoder: out[e] = dot(X[u], X[v]) ----------------
__global__ void k_decode(const float* __restrict__ X, const int* __restrict__ eli,
                         float* __restrict__ out, int EL) {
    int gt   = blockIdx.x * blockDim.x + threadIdx.x;
    int e    = gt >> 5;
    int lane = gt & 31;
    if (e >= EL) return;
    int u = eli[e];
    int v = eli[EL + e];
    const float4* X4 = (const float4*)X;
    float4 a = X4[(size_t)u * 32 + lane];
    float4 b = X4[(size_t)v * 32 + lane];
    float s = a.x * b.x + a.y * b.y + a.z * b.z + a.w * b.w;
    #pragma unroll
    for (int o = 16; o > 0; o >>= 1) s += __shfl_xor_sync(0xffffffffu, s, o);
    if (lane == 0) out[e] = s;
}

// ---------------- launch ----------------
extern "C" void kernel_launch(void* const* d_in, const int* in_sizes, int n_in,
                              void* d_out, int out_size) {
    const float* x   = (const float*)d_in[0];
    const float* W1  = (const float*)d_in[1];
    const float* b1  = (const float*)d_in[2];
    const float* W2  = (const float*)d_in[3];
    const float* b2  = (const float*)d_in[4];
    const float* W3  = (const float*)d_in[5];
    const float* b3  = (const float*)d_in[6];
    const int*   ei  = (const int*)d_in[7];
    const int*   eli = (const int*)d_in[8];
    float*       out = (float*)d_out;

    int N  = in_sizes[0] / D;
    int E  = in_sizes[7] / 2;
    int EL = in_sizes[8] / 2;

    float *pH, *pA, *pB;
    uint32_t *pWh, *pWl;
    cudaGetSymbolAddress((void**)&pH,  g_H);
    cudaGetSymbolAddress((void**)&pA,  g_A);
    cudaGetSymbolAddress((void**)&pB,  g_B);
    cudaGetSymbolAddress((void**)&pWh, g_Wh);
    cudaGetSymbolAddress((void**)&pWl, g_Wl);

    cudaFuncSetAttribute(k_gemm_mma, cudaFuncAttributeMaxDynamicSharedMemorySize,
                         GEMM_SMEM);

    int nb          = (N + 1023) / 1024;
    int gemm_blocks = (N + 127) / 128;
    int agg_blocks  = (int)(((size_t)N * 32 + 255) / 256);

    // ---- fork: CSR build on s2, concurrent with W-split + GEMM-1 on stream 0 ----
    cudaEventRecord(evFork, 0);
    cudaStreamWaitEvent(s2, evFork, 0);
    k_count  <<<(E / 4 + 255) / 256, 256, 0, s2>>>(ei + E, E);
    k_scan_lb<<<nb, 1024, 0, s2>>>(N);
    k_fill   <<<(E / 4 + 255) / 256, 256, 0, s2>>>(ei, E);
    cudaEventRecord(evJoin, s2);

    // ---- W pre-split (all layers) then layer-1 GEMM, overlapping CSR ----
    k_wsplit<<<dim3(32, 3), 256>>>(W1, W2, W3);
    k_gemm_mma<<<gemm_blocks, 256, GEMM_SMEM>>>(x, pWh, pWl, pH, N);

    // ---- join: agg needs both GEMM-1 output and the CSR ----
    cudaStreamWaitEvent(0, evJoin, 0);
    k_agg<<<agg_blocks, 256>>>(b1, pA, N, 1);

    // ---- layer 2 ----
    k_gemm_mma<<<gemm_blocks, 256, GEMM_SMEM>>>(pA, pWh + 8192, pWl + 8192, pH, N);
    k_agg<<<agg_blocks, 256>>>(b2, pB, N, 1);

    // ---- layer 3 (no relu) ----
    k_gemm_mma<<<gemm_blocks, 256, GEMM_SMEM>>>(pB, pWh + 16384, pWl + 16384, pH, N);
    k_agg<<<agg_blocks, 256>>>(b3, pA, N, 0);

    // ---- decoder ----
    k_decode<<<(int)(((size_t)EL * 32 + 255) / 256), 256>>>(pA, eli, out, EL);
}

// round 16
// speedup vs baseline: 1.3574x; 1.0328x over previous
#include <cuda_runtime.h>
#include <cuda_bf16.h>
#include <cuda_fp16.h>
#include <cstdint>

#define D 128
#define NMAX 50000
#define EMAX 800000

// ---------------- scratch (static device globals; no allocation) ----------------
__device__ uint32_t g_H [(size_t)NMAX * 64]; // GEMM output per layer, fp16x2 packed
__device__ float    g_A [(size_t)NMAX * D];  // layer activations (ping), fp32
__device__ float    g_B [(size_t)NMAX * D];  // layer activations (pong), fp32
__device__ uint32_t g_Wh[3 * 64 * 128];      // W hi, packed bf16 k-pairs [p][n]
__device__ uint32_t g_Wl[3 * 64 * 128];      // W lo, packed bf16 k-pairs
__device__ float    g_dinv[NMAX];
__device__ int      g_cnt[NMAX];             // invariant: zero at entry
__device__ int      g_rowstart[NMAX + 1];
__device__ int      g_cursor[NMAX];
__device__ int2     g_cw[EMAX];              // packed (src, weight-bits)
__device__ unsigned long long g_desc[64];    // lookback descriptors (zero at entry)

// ---------------- capture-safe static stream/events (host resources only) ------
static cudaStream_t s2;
static cudaEvent_t  evFork, evJoin;
namespace { struct _Init {
    _Init() {
        cudaStreamCreateWithFlags(&s2, cudaStreamNonBlocking);
        cudaEventCreateWithFlags(&evFork, cudaEventDisableTiming);
        cudaEventCreateWithFlags(&evJoin, cudaEventDisableTiming);
    }
} _init; }

// ---------------- bf16 / mma / async helpers ----------------
__device__ __forceinline__ void bf16_split2(float2 v, uint32_t& hp, uint32_t& lp) {
    __nv_bfloat162 h2 = __float22bfloat162_rn(v);          // low=v.x, high=v.y
    float2 r = make_float2(v.x - __low2float(h2), v.y - __high2float(h2));
    __nv_bfloat162 l2 = __float22bfloat162_rn(r);
    hp = *reinterpret_cast<uint32_t*>(&h2);
    lp = *reinterpret_cast<uint32_t*>(&l2);
}

__device__ __forceinline__ void mma_bf16(float* c, const uint32_t* a,
                                         uint32_t b0, uint32_t b1) {
    asm volatile(
        "mma.sync.aligned.m16n8k16.row.col.f32.bf16.bf16.f32 "
        "{%0,%1,%2,%3}, {%4,%5,%6,%7}, {%8,%9}, {%0,%1,%2,%3};"
        : "+f"(c[0]), "+f"(c[1]), "+f"(c[2]), "+f"(c[3])
        : "r"(a[0]), "r"(a[1]), "r"(a[2]), "r"(a[3]), "r"(b0), "r"(b1));
}

__device__ __forceinline__ void cp_async16(uint32_t saddr, const void* gptr) {
    asm volatile("cp.async.cg.shared.global [%0], [%1], 16;"
                 :: "r"(saddr), "l"(gptr));
}

// unpack 4 halves (uint2) -> float4
__device__ __forceinline__ float4 h4_to_f4(uint2 p) {
    __half2 a = *reinterpret_cast<__half2*>(&p.x);
    __half2 b = *reinterpret_cast<__half2*>(&p.y);
    float2 fa = __half22float2(a);
    float2 fb = __half22float2(b);
    return make_float4(fa.x, fa.y, fb.x, fb.y);
}

// ---------------- W pre-split: pack bf16 k-pairs, all 3 layers ----------------
__global__ void k_wsplit(const float* __restrict__ W1,
                         const float* __restrict__ W2,
                         const float* __restrict__ W3) {
    int layer = blockIdx.y;
    const float* W = (layer == 0) ? W1 : (layer == 1) ? W2 : W3;
    int i = blockIdx.x * 256 + threadIdx.x;      // 0..8191 (grid.x = 32)
    int p = i >> 7, n = i & 127;
    float x0 = W[(2 * p) * D + n];
    float x1 = W[(2 * p + 1) * D + n];
    uint32_t hp, lp;
    bf16_split2(make_float2(x0, x1), hp, lp);
    g_Wh[layer * 8192 + i] = hp;
    g_Wl[layer * 8192 + i] = lp;
}

// ---------------- CSR construction ----------------
__global__ void k_count(const int* __restrict__ dst, int E) {
    int base = (blockIdx.x * blockDim.x + threadIdx.x) * 4;
    if (base >= E) return;
    if (base + 3 < E) {
        int4 d = *(const int4*)(dst + base);
        atomicAdd(&g_cnt[d.x], 1);
        atomicAdd(&g_cnt[d.y], 1);
        atomicAdd(&g_cnt[d.z], 1);
        atomicAdd(&g_cnt[d.w], 1);
    } else {
        for (int j = base; j < E; j++) atomicAdd(&g_cnt[dst[j]], 1);
    }
}

// single-pass exclusive scan via decoupled lookback; self-cleans g_cnt.
__global__ void k_scan_lb(int n) {
    __shared__ int wsum[32];
    __shared__ int s_prefix;
    int tid = threadIdx.x, lane = tid & 31, wid = tid >> 5;
    int b = blockIdx.x;
    int i = b * 1024 + tid;
    int v = (i < n) ? g_cnt[i] : 0;
    if (i < n) g_cnt[i] = 0;               // self-clean for next replay
    int x = v;
    #pragma unroll
    for (int o = 1; o < 32; o <<= 1) {
        int t = __shfl_up_sync(0xffffffffu, x, o);
        if (lane >= o) x += t;
    }
    if (lane == 31) wsum[wid] = x;
    __syncthreads();
    if (wid == 0) {
        int w = wsum[lane];
        #pragma unroll
        for (int o = 1; o < 32; o <<= 1) {
            int t = __shfl_up_sync(0xffffffffu, w, o);
            if (lane >= o) w += t;
        }
        wsum[lane] = w;
    }
    __syncthreads();
    int blockAgg = wsum[31];

    if (tid == 0) {
        if (b == 0) {
            s_prefix = 0;
            atomicExch(&g_desc[0], (2ULL << 32) | (unsigned)blockAgg);
        } else {
            atomicExch(&g_desc[b], (1ULL << 32) | (unsigned)blockAgg);
        }
    }
    if (b > 0 && wid == 0) {
        int prefix = 0;
        int look = b - 1;
        while (true) {
            int idx = look - lane;
            unsigned f; int val;
            if (idx >= 0) {
                unsigned long long d = atomicAdd(&g_desc[idx], 0ULL);
                f = (unsigned)(d >> 32);
                val = (int)(unsigned)d;
            } else { f = 1u; val = 0; }
            if (__ballot_sync(0xffffffffu, f == 0u)) continue;   // retry window
            unsigned bp = __ballot_sync(0xffffffffu, idx >= 0 && f == 2u);
            int stop = bp ? (__ffs(bp) - 1) : 32;
            int xs = (lane <= stop) ? val : 0;
            #pragma unroll
            for (int o = 16; o > 0; o >>= 1)
                xs += __shfl_xor_sync(0xffffffffu, xs, o);
            prefix += xs;
            if (stop < 32) break;
            look -= 32;
        }
        if (lane == 0) {
            s_prefix = prefix;
            atomicExch(&g_desc[b], (2ULL << 32) | (unsigned)(prefix + blockAgg));
        }
    }
    __syncthreads();

    int excl = s_prefix + (wid ? wsum[wid - 1] : 0) + x - v;
    if (i < n) {
        g_rowstart[i] = excl;
        g_cursor[i]   = excl;
        g_dinv[i]     = rsqrtf((float)(v + 1));   // deg incl. self-loop
        if (i == n - 1) g_rowstart[n] = excl + v;
    }
}

__global__ void k_fill(const int* __restrict__ ei, int E) {
    if (blockIdx.x == 0 && threadIdx.x < 64) g_desc[threadIdx.x] = 0ULL;
    int base = (blockIdx.x * blockDim.x + threadIdx.x) * 4;
    if (base >= E) return;
    if (base + 3 < E) {
        int4 s = *(const int4*)(ei + base);
        int4 d = *(const int4*)(ei + E + base);
        int ss[4] = {s.x, s.y, s.z, s.w};
        int ds[4] = {d.x, d.y, d.z, d.w};
        float ws[4];
        #pragma unroll
        for (int j = 0; j < 4; j++) ws[j] = g_dinv[ss[j]] * g_dinv[ds[j]];
        #pragma unroll
        for (int j = 0; j < 4; j++) {
            int p = atomicAdd(&g_cursor[ds[j]], 1);
            g_cw[p] = make_int2(ss[j], __float_as_int(ws[j]));
        }
    } else {
        for (int j = base; j < E; j++) {
            int sj = ei[j], dj = ei[E + j];
            float w = g_dinv[sj] * g_dinv[dj];
            int p = atomicAdd(&g_cursor[dj], 1);
            g_cw[p] = make_int2(sj, __float_as_int(w));
        }
    }
}

// ---------------- GEMM: H[M x 128] = X @ W via 3x bf16 mma.m16n8k16 -------------
// R15-measured structure; epilogue now stores fp16 pairs (halves agg gather bytes).
#define SXB 36    // X smem row stride (uint32 pairs): A bank = (4g+t)%32 bijective
#define SWB 136   // W smem row stride (uint32):       B bank = (8t+g)%32 bijective
#define GEMM_SMEM ((2 * 128 * SXB + 2 * 64 * SWB) * (int)sizeof(uint32_t))

__global__ __launch_bounds__(256, 1)
void k_gemm_mma(const float* __restrict__ X,
                const uint32_t* __restrict__ Wh, const uint32_t* __restrict__ Wl,
                __half2* __restrict__ H, int M) {
    extern __shared__ uint32_t smu[];
    uint32_t* sXh = smu;
    uint32_t* sXl = sXh + 128 * SXB;
    uint32_t* sWh = sXl + 128 * SXB;        // full K: 64 pair-rows
    uint32_t* sWl = sWh + 64 * SWB;

    const int tid  = threadIdx.x;
    const int lane = tid & 31;
    const int g    = lane >> 2;
    const int t    = lane & 3;
    const int warp = tid >> 5;
    const int wm   = (warp >> 1) * 32;   // warp M offset
    const int wn   = (warp & 1) * 64;    // warp N offset
    const int row0 = blockIdx.x * 128;

    // ---- async copy of both W splits (full K, pre-packed; pure copy)
    {
        uint32_t swh = (uint32_t)__cvta_generic_to_shared(sWh);
        uint32_t swl = (uint32_t)__cvta_generic_to_shared(sWl);
        #pragma unroll
        for (int it = 0; it < 8; it++) {
            int e4 = tid + it * 256;        // 0..2047 (16B chunks)
            int r  = e4 >> 5;               // pair row 0..63
            int c4 = (e4 & 31) * 4;         // n col (x4 uint32)
            cp_async16(swh + (uint32_t)(r * SWB + c4) * 4, Wh + r * 128 + c4);
            cp_async16(swl + (uint32_t)(r * SWB + c4) * 4, Wl + r * 128 + c4);
        }
        asm volatile("cp.async.commit_group;");
    }

    float acc[2][8][4];
    #pragma unroll
    for (int a = 0; a < 2; a++)
        #pragma unroll
        for (int b = 0; b < 8; b++)
            #pragma unroll
            for (int c = 0; c < 4; c++) acc[a][b][c] = 0.f;

    #pragma unroll
    for (int kc = 0; kc < 2; kc++) {
        // load + split X chunk [128 rows][64 k = 32 pairs]
        #pragma unroll
        for (int it = 0; it < 8; it++) {
            int e4 = tid + it * 256;        // 0..2047
            int r  = e4 >> 4;               // row 0..127
            int c4 = e4 & 15;               // float4 index in row
            float4 v = make_float4(0.f, 0.f, 0.f, 0.f);
            if (row0 + r < M)
                v = *(const float4*)&X[(size_t)(row0 + r) * D + kc * 64 + c4 * 4];
            uint32_t hp0, lp0, hp1, lp1;
            bf16_split2(make_float2(v.x, v.y), hp0, lp0);
            bf16_split2(make_float2(v.z, v.w), hp1, lp1);
            *(uint2*)&sXh[r * SXB + c4 * 2] = make_uint2(hp0, hp1);
            *(uint2*)&sXl[r * SXB + c4 * 2] = make_uint2(lp0, lp1);
        }
        if (kc == 0) asm volatile("cp.async.wait_group 0;");
        __syncthreads();

        #pragma unroll
        for (int ks = 0; ks < 4; ks++) {       // 4 x K16 per 64-k chunk
            int kp  = ks * 8;                  // pair offset in chunk
            int kgp = kc * 32 + kp;            // global W pair row
            uint32_t ah[2][4], al[2][4];
            #pragma unroll
            for (int mi = 0; mi < 2; mi++) {
                int mb = wm + mi * 16;
                ah[mi][0] = sXh[(mb + g)     * SXB + kp + t];
                ah[mi][1] = sXh[(mb + g + 8) * SXB + kp + t];
                ah[mi][2] = sXh[(mb + g)     * SXB + kp + t + 4];
                ah[mi][3] = sXh[(mb + g + 8) * SXB + kp + t + 4];
                al[mi][0] = sXl[(mb + g)     * SXB + kp + t];
                al[mi][1] = sXl[(mb + g + 8) * SXB + kp + t];
                al[mi][2] = sXl[(mb + g)     * SXB + kp + t + 4];
                al[mi][3] = sXl[(mb + g + 8) * SXB + kp + t + 4];
            }
            #pragma unroll
            for (int j = 0; j < 8; j++) {
                int nb = wn + j * 8;
                uint32_t bh0 = sWh[(kgp + t)     * SWB + nb + g];
                uint32_t bh1 = sWh[(kgp + t + 4) * SWB + nb + g];
                uint32_t bl0 = sWl[(kgp + t)     * SWB + nb + g];
                uint32_t bl1 = sWl[(kgp + t + 4) * SWB + nb + g];
                #pragma unroll
                for (int mi = 0; mi < 2; mi++) {
                    mma_bf16(acc[mi][j], ah[mi], bh0, bh1);
                    mma_bf16(acc[mi][j], ah[mi], bl0, bl1);
                    mma_bf16(acc[mi][j], al[mi], bh0, bh1);
                }
            }
        }
        __syncthreads();
    }

    // epilogue: store fp16 pairs (64 half2 per row)
    #pragma unroll
    for (int mi = 0; mi < 2; mi++) {
        int r0 = row0 + wm + mi * 16 + g;
        #pragma unroll
        for (int j = 0; j < 8; j++) {
            int colp = (wn + j * 8 + 2 * t) >> 1;   // half2 index in row
            if (r0 < M)
                H[(size_t)r0 * 64 + colp] =
                    __floats2half2_rn(acc[mi][j][0], acc[mi][j][1]);
            if (r0 + 8 < M)
                H[(size_t)(r0 + 8) * 64 + colp] =
                    __floats2half2_rn(acc[mi][j][2], acc[mi][j][3]);
        }
    }
}

// ---------------- aggregation: Y[n] = relu?( dinv^2*H[n] + sum w_i*H[col_i] + b )
// H is fp16-packed: 32 x uint2 per row (8B per lane), halving gather traffic.
__global__ void k_agg(const float* __restrict__ bias, float* __restrict__ Y,
                      int n, int do_relu) {
    int gt   = blockIdx.x * blockDim.x + threadIdx.x;
    int node = gt >> 5;
    int lane = gt & 31;
    if (node >= n) return;

    const uint2* H2 = (const uint2*)g_H;
    float di = g_dinv[node];
    float sw = di * di;
    float4 hs = h4_to_f4(H2[(size_t)node * 32 + lane]);
    float4 acc = make_float4(hs.x * sw, hs.y * sw, hs.z * sw, hs.w * sw);

    int i   = g_rowstart[node];
    int end = g_rowstart[node + 1];
    for (; i + 3 < end; i += 4) {
        int2  e0 = g_cw[i],     e1 = g_cw[i + 1];
        int2  e2 = g_cw[i + 2], e3 = g_cw[i + 3];
        float w0 = __int_as_float(e0.y), w1 = __int_as_float(e1.y);
        float w2 = __int_as_float(e2.y), w3 = __int_as_float(e3.y);
        float4 h0 = h4_to_f4(H2[(size_t)e0.x * 32 + lane]);
        float4 h1 = h4_to_f4(H2[(size_t)e1.x * 32 + lane]);
        float4 h2 = h4_to_f4(H2[(size_t)e2.x * 32 + lane]);
        float4 h3 = h4_to_f4(H2[(size_t)e3.x * 32 + lane]);
        acc.x += w0 * h0.x + w1 * h1.x + w2 * h2.x + w3 * h3.x;
        acc.y += w0 * h0.y + w1 * h1.y + w2 * h2.y + w3 * h3.y;
        acc.z += w0 * h0.z + w1 * h1.z + w2 * h2.z + w3 * h3.z;
        acc.w += w0 * h0.w + w1 * h1.w + w2 * h2.w + w3 * h3.w;
    }
    for (; i < end; i++) {
        int2  e = g_cw[i];
        float w = __int_as_float(e.y);
        float4 h = h4_to_f4(H2[(size_t)e.x * 32 + lane]);
        acc.x += w * h.x; acc.y += w * h.y; acc.z += w * h.z; acc.w += w * h.w;
    }

    float4 b4 = ((const float4*)bias)[lane];
    acc.x += b4.x; acc.y += b4.y; acc.z += b4.z; acc.w += b4.w;
    if (do_relu) {
        acc.x = fmaxf(acc.x, 0.f); acc.y = fmaxf(acc.y, 0.f);
        acc.z = fmaxf(acc.z, 0.f); acc.w = fmaxf(acc.w, 0.f);
    }
    ((float4*)Y)[(size_t)node * 32 + lane] = acc;
}

// ---------------- decoder: out[e] = dot(X[u], X[v]) ----------------
__global__ void k_decode(const float* __restrict__ X, const int* __restrict__ eli,
                         float* __restrict__ out, int EL) {
    int gt   = blockIdx.x * blockDim.x + threadIdx.x;
    int e    = gt >> 5;
    int lane = gt & 31;
    if (e >= EL) return;
    int u = eli[e];
    int v = eli[EL + e];
    const float4* X4 = (const float4*)X;
    float4 a = X4[(size_t)u * 32 + lane];
    float4 b = X4[(size_t)v * 32 + lane];
    float s = a.x * b.x + a.y * b.y + a.z * b.z + a.w * b.w;
    #pragma unroll
    for (int o = 16; o > 0; o >>= 1) s += __shfl_xor_sync(0xffffffffu, s, o);
    if (lane == 0) out[e] = s;
}

// ---------------- launch ----------------
extern "C" void kernel_launch(void* const* d_in, const int* in_sizes, int n_in,
                              void* d_out, int out_size) {
    const float* x   = (const float*)d_in[0];
    const float* W1  = (const float*)d_in[1];
    const float* b1  = (const float*)d_in[2];
    const float* W2  = (const float*)d_in[3];
    const float* b2  = (const float*)d_in[4];
    const float* W3  = (const float*)d_in[5];
    const float* b3  = (const float*)d_in[6];
    const int*   ei  = (const int*)d_in[7];
    const int*   eli = (const int*)d_in[8];
    float*       out = (float*)d_out;

    int N  = in_sizes[0] / D;
    int E  = in_sizes[7] / 2;
    int EL = in_sizes[8] / 2;

    float *pA, *pB;
    __half2* pH;
    uint32_t *pWh, *pWl;
    cudaGetSymbolAddress((void**)&pH,  g_H);
    cudaGetSymbolAddress((void**)&pA,  g_A);
    cudaGetSymbolAddress((void**)&pB,  g_B);
    cudaGetSymbolAddress((void**)&pWh, g_Wh);
    cudaGetSymbolAddress((void**)&pWl, g_Wl);

    cudaFuncSetAttribute(k_gemm_mma, cudaFuncAttributeMaxDynamicSharedMemorySize,
                         GEMM_SMEM);

    int nb          = (N + 1023) / 1024;
    int gemm_blocks = (N + 127) / 128;
    int agg_blocks  = (int)(((size_t)N * 32 + 255) / 256);

    // ---- fork: CSR build on s2, concurrent with W-split + GEMM-1 on stream 0 ----
    cudaEventRecord(evFork, 0);
    cudaStreamWaitEvent(s2, evFork, 0);
    k_count  <<<(E / 4 + 255) / 256, 256, 0, s2>>>(ei + E, E);
    k_scan_lb<<<nb, 1024, 0, s2>>>(N);
    k_fill   <<<(E / 4 + 255) / 256, 256, 0, s2>>>(ei, E);
    cudaEventRecord(evJoin, s2);

    // ---- W pre-split (all layers) then layer-1 GEMM, overlapping CSR ----
    k_wsplit<<<dim3(32, 3), 256>>>(W1, W2, W3);
    k_gemm_mma<<<gemm_blocks, 256, GEMM_SMEM>>>(x, pWh, pWl, pH, N);

    // ---- join: agg needs both GEMM-1 output and the CSR ----
    cudaStreamWaitEvent(0, evJoin, 0);
    k_agg<<<agg_blocks, 256>>>(b1, pA, N, 1);

    // ---- layer 2 ----
    k_gemm_mma<<<gemm_blocks, 256, GEMM_SMEM>>>(pA, pWh + 8192, pWl + 8192, pH, N);
    k_agg<<<agg_blocks, 256>>>(b2, pB, N, 1);

    // ---- layer 3 (no relu) ----
    k_gemm_mma<<<gemm_blocks, 256, GEMM_SMEM>>>(pB, pWh + 16384, pWl + 16384, pH, N);
    k_agg<<<agg_blocks, 256>>>(b3, pA, N, 0);

    // ---- decoder ----
    k_decode<<<(int)(((size_t)EL * 32 + 255) / 256), 256>>>(pA, eli, out, EL);
}